// round 10
// baseline (speedup 1.0000x reference)
#include <cuda_runtime.h>
#include <cstdint>

// Embedding gather: LDGSTS gather + TMA bulk store, double-buffered (sm_103a).
// x: [32768] int32; emb: [50257, 512] f32; out: [32768, 512] f32.
// even ids -> id 0 (reference: jnp.where(x % 2 == 0, 0, x)).
//
// Read side:  cp.async.ca 16B gathers a 16-row (32KB) tile into smem --
//             no register writeback, no scoreboard stall per load.
// Write side: output tiles are contiguous 32KB blocks -> one TMA bulk store
//             per tile (UBLKCP), bypassing L1tex + RF on the store side.
// Double buffering: fills of tile j+1 overlap the store of tile j.
// Persistent grid (444 CTAs = 3/SM at 66KB smem), ~5 tiles per CTA.

static constexpr int ROW_BYTES  = 2048;                 // 512 f32
static constexpr int TILE_ROWS  = 16;
static constexpr int TILE_BYTES = TILE_ROWS * ROW_BYTES;  // 32768
static constexpr int THREADS    = 256;
static constexpr int GRID       = 444;                  // 3 per SM
static constexpr int MAXT       = 8;                    // >= ceil(2048/444)

__device__ __forceinline__ uint32_t smem_u32(const void* p) {
    return (uint32_t)__cvta_generic_to_shared(p);
}

__global__ __launch_bounds__(THREADS)
void embed_pipe_kernel(const int* __restrict__ x,
                       const char* __restrict__ emb,
                       char* __restrict__ out,
                       int n_tiles) {
    __shared__ alignas(128) char buf[2][TILE_BYTES];
    __shared__ int toks[MAXT][TILE_ROWS];

    const int tid = threadIdx.x;
    const int G   = gridDim.x;
    const int b   = blockIdx.x;
    const int nt  = (n_tiles - b + G - 1) / G;   // tiles this CTA handles
    if (nt <= 0) return;

    // Preload + remap ALL token ids this CTA will need (<= MAXT*16 ints).
    for (int idx = tid; idx < nt * TILE_ROWS; idx += THREADS) {
        int j   = idx >> 4;
        int r   = idx & 15;
        int row = (b + j * G) * TILE_ROWS + r;
        int tok = x[row];
        toks[j][r] = (tok & 1) ? tok : 0;        // even ids -> row 0
    }
    __syncthreads();

    // Per-thread fill of one tile: 8 x cp.async 16B, flat index i=c*256+tid,
    // row = i>>7, col = i&127; smem layout == gmem layout of the out tile.
    auto fill = [&](int j, int bsel) {
        const uint32_t s0 = smem_u32(&buf[bsel][0]);
#pragma unroll
        for (int c = 0; c < TILE_BYTES / (THREADS * 16); c++) {
            int i   = c * THREADS + tid;
            int row = i >> 7;
            int col = i & 127;
            const char* src = emb + (size_t)toks[j][row] * ROW_BYTES + col * 16;
            uint32_t dst = s0 + (uint32_t)i * 16;
            asm volatile("cp.async.ca.shared.global [%0], [%1], 16;"
                         :: "r"(dst), "l"(src) : "memory");
        }
        asm volatile("cp.async.commit_group;" ::: "memory");
    };

    // Prologue: start tile 0 into buf[0].
    fill(0, 0);

    for (int j = 0; j < nt; j++) {
        const int A = j & 1;

        if (j + 1 < nt) {
            // buf[A^1] was bulk-stored at iteration j-1; ensure that store
            // has finished READING smem before we overwrite it.
            if (j >= 1) {
                if (tid == 0)
                    asm volatile("cp.async.bulk.wait_group.read 0;" ::: "memory");
                __syncthreads();
            }
            fill(j + 1, A ^ 1);
            // Tile j's group done; tile j+1's may stay in flight.
            asm volatile("cp.async.wait_group 1;" ::: "memory");
        } else {
            asm volatile("cp.async.wait_group 0;" ::: "memory");
        }
        __syncthreads();   // tile j's fills visible CTA-wide

        if (tid == 0) {
            asm volatile("fence.proxy.async.shared::cta;" ::: "memory");
            char* dst = out + (size_t)(b + j * G) * TILE_BYTES;
            const uint32_t s0 = smem_u32(&buf[A][0]);
            asm volatile(
                "cp.async.bulk.global.shared::cta.bulk_group [%0], [%1], %2;"
                :: "l"(dst), "r"(s0), "n"(TILE_BYTES) : "memory");
            asm volatile("cp.async.bulk.commit_group;" ::: "memory");
        }
    }

    // All bulk stores must complete before CTA exit.
    if (tid == 0)
        asm volatile("cp.async.bulk.wait_group 0;" ::: "memory");
}

extern "C" void kernel_launch(void* const* d_in, const int* in_sizes, int n_in,
                              void* d_out, int out_size) {
    const int* x    = (const int*)d_in[0];
    const char* emb = (const char*)d_in[1];
    char* out       = (char*)d_out;

    int n_rows  = in_sizes[0];              // 32768
    int n_tiles = n_rows / TILE_ROWS;       // 2048

    embed_pipe_kernel<<<GRID, THREADS>>>(x, emb, out, n_tiles);
}

// round 11
// speedup vs baseline: 1.0187x; 1.0187x over previous
#include <cuda_runtime.h>
#include <cstdint>

// Embedding gather: LDG.128 reads -> smem -> single TMA bulk store per tile.
// x: [32768] int32; emb: [50257, 512] f32; out: [32768, 512] f32.
// even ids -> id 0 (reference: jnp.where(x % 2 == 0, 0, x)).
//
// Read side:  proven MLP-8 LDG.128 path (8 independent loads/thread).
// Write side: STS.128 into a 32KB smem tile laid out exactly like the
//             contiguous 16-row output block, then ONE cp.async.bulk
//             (UBLKCP) ships it gmem-ward -- no STG.128 issue cost, no
//             L1tex wavefronts on the store side at all.

static constexpr int VEC_PER_ROW    = 128;   // float4 per row
static constexpr int ROWS_PER_BLOCK = 16;
static constexpr int THREADS        = 256;
static constexpr int TILE_VECS      = ROWS_PER_BLOCK * VEC_PER_ROW;  // 2048
static constexpr int TILE_BYTES     = TILE_VECS * 16;                // 32768

__device__ __forceinline__ uint32_t smem_u32(const void* p) {
    return (uint32_t)__cvta_generic_to_shared(p);
}

__global__ __launch_bounds__(THREADS)
void embed_gather_kernel(const int* __restrict__ x,
                         const float4* __restrict__ emb,
                         float4* __restrict__ out,
                         int n_rows) {
    __shared__ alignas(128) float4 stage[TILE_VECS];   // 32 KB
    __shared__ int toks[ROWS_PER_BLOCK];

    const int base = blockIdx.x * ROWS_PER_BLOCK;
    const int tid  = threadIdx.x;

    if (tid < ROWS_PER_BLOCK) {
        int r = base + tid;
        int tok = (r < n_rows) ? x[r] : 0;
        toks[tid] = (tok & 1) ? tok : 0;   // even ids -> row 0
    }
    __syncthreads();

    // chunk c covers rows {2c, 2c+1}: threads 0..127 -> row 2c,
    // threads 128..255 -> row 2c+1; col = tid & 127 (fully coalesced).
    const int rhi = tid >> 7;
    const int col = tid & 127;

    float4 v0 = __ldg(emb + (size_t)toks[ 0 + rhi] * VEC_PER_ROW + col);
    float4 v1 = __ldg(emb + (size_t)toks[ 2 + rhi] * VEC_PER_ROW + col);
    float4 v2 = __ldg(emb + (size_t)toks[ 4 + rhi] * VEC_PER_ROW + col);
    float4 v3 = __ldg(emb + (size_t)toks[ 6 + rhi] * VEC_PER_ROW + col);
    float4 v4 = __ldg(emb + (size_t)toks[ 8 + rhi] * VEC_PER_ROW + col);
    float4 v5 = __ldg(emb + (size_t)toks[10 + rhi] * VEC_PER_ROW + col);
    float4 v6 = __ldg(emb + (size_t)toks[12 + rhi] * VEC_PER_ROW + col);
    float4 v7 = __ldg(emb + (size_t)toks[14 + rhi] * VEC_PER_ROW + col);

    // smem tile layout == gmem layout of the 16 consecutive output rows:
    // chunk c's flat float4 index = c*256 + tid.
    stage[0 * THREADS + tid] = v0;
    stage[1 * THREADS + tid] = v1;
    stage[2 * THREADS + tid] = v2;
    stage[3 * THREADS + tid] = v3;
    stage[4 * THREADS + tid] = v4;
    stage[5 * THREADS + tid] = v5;
    stage[6 * THREADS + tid] = v6;
    stage[7 * THREADS + tid] = v7;

    __syncthreads();   // all STS visible before the async-proxy read

    if (tid == 0) {
        // Order generic-proxy smem writes before async-proxy (TMA) read.
        asm volatile("fence.proxy.async.shared::cta;" ::: "memory");
        char* dst = (char*)(out + (size_t)base * VEC_PER_ROW);
        const uint32_t s0 = smem_u32(stage);
        asm volatile(
            "cp.async.bulk.global.shared::cta.bulk_group [%0], [%1], %2;"
            :: "l"(dst), "r"(s0), "n"(TILE_BYTES) : "memory");
        asm volatile("cp.async.bulk.commit_group;" ::: "memory");
        // Store must complete before this CTA's smem can be retired.
        asm volatile("cp.async.bulk.wait_group 0;" ::: "memory");
    }
}

extern "C" void kernel_launch(void* const* d_in, const int* in_sizes, int n_in,
                              void* d_out, int out_size) {
    const int* x      = (const int*)d_in[0];
    const float4* emb = (const float4*)d_in[1];
    float4* out       = (float4*)d_out;

    int n_rows   = in_sizes[0];  // 32768
    int n_blocks = (n_rows + ROWS_PER_BLOCK - 1) / ROWS_PER_BLOCK;  // 2048

    embed_gather_kernel<<<n_blocks, THREADS>>>(x, emb, out, n_rows);
}